// round 16
// baseline (speedup 1.0000x reference)
#include <cuda_runtime.h>
#include <stdint.h>
#include <math.h>

// Inputs: 0 v_data f32[524288*16], 1 cond f32[524288], 2 W f32[16*32], 3 b f32[16],
// 4 c f32[32], 5 W1 f32[64], 6 b1 f32[64], 7 W2 f32[64*96], 8 b2 f32[96], 9 k int[1]
// output: f32[1]

#define NV 16
#define NH 32
#define TPB 128
#define MAXK 64
#define MAXBLK 8192

typedef unsigned long long u64;

#define NEG_LOG2E (-1.44269504088896340736f)
#define NLN2      (-0.69314718055994530942f)
#define LN2       (0.69314718055994530942f)
#define TWO32F    4294967296.0f
#define ONES2     0x3F8000003F800000ull

__device__ float g_part[MAXBLK];
__device__ unsigned int g_ticket;   // zero-init; reset by last block each launch

// ---------------------------------------------------------------------------
// threefry2x32 (JAX partitionable semantics, verified bit-exact)
// ---------------------------------------------------------------------------
__device__ __forceinline__ uint32_t rotl32(uint32_t x, int r) {
    return __funnelshift_l(x, x, r);
}

__device__ __forceinline__ uint2 tf2x32(uint2 key, uint32_t chi, uint32_t clo) {
    uint32_t k0 = key.x, k1 = key.y, k2 = k0 ^ k1 ^ 0x1BD11BDAu;
    uint32_t x0 = chi + k0, x1 = clo + k1;
#define TFR(r) { x0 += x1; x1 = rotl32(x1, r); x1 ^= x0; }
    TFR(13) TFR(15) TFR(26) TFR(6)   x0 += k1; x1 += k2 + 1u;
    TFR(17) TFR(29) TFR(16) TFR(24)  x0 += k2; x1 += k0 + 2u;
    TFR(13) TFR(15) TFR(26) TFR(6)   x0 += k0; x1 += k1 + 3u;
    TFR(17) TFR(29) TFR(16) TFR(24)  x0 += k1; x1 += k2 + 4u;
    TFR(13) TFR(15) TFR(26) TFR(6)   x0 += k2; x1 += k0 + 5u;
#undef TFR
    return make_uint2(x0, x1);
}

struct TFK { uint32_t k0, k1, k2, c1, c2, c3, c4, c5; };

__device__ __forceinline__ TFK mk_tfk(uint2 key) {
    TFK K;
    K.k0 = key.x; K.k1 = key.y; K.k2 = K.k0 ^ K.k1 ^ 0x1BD11BDAu;
    K.c1 = K.k2 + 1u; K.c2 = K.k0 + 2u; K.c3 = K.k1 + 3u;
    K.c4 = K.k2 + 4u; K.c5 = K.k0 + 5u;
    return K;
}

// x1init = idx + K.k1 precombined by caller (integer add exact)
__device__ __forceinline__ uint32_t tf_bits_pc(const TFK K, uint32_t x1init) {
    uint32_t x0 = K.k0, x1 = x1init;
#define TFR(r) { x0 += x1; x1 = rotl32(x1, r); x1 ^= x0; }
    TFR(13) TFR(15) TFR(26) TFR(6)   x0 += K.k1; x1 += K.c1;
    TFR(17) TFR(29) TFR(16) TFR(24)  x0 += K.k2; x1 += K.c2;
    TFR(13) TFR(15) TFR(26) TFR(6)   x0 += K.k0; x1 += K.c3;
    TFR(17) TFR(29) TFR(16) TFR(24)  x0 += K.k1; x1 += K.c4;
    TFR(13) TFR(15) TFR(26) TFR(6)   x0 += K.k2; x1 += K.c5;
#undef TFR
    return x0 ^ x1;
}

// raw ex2.approx: input pre-scaled by -log2e, result = e^{-s}
__device__ __forceinline__ float ex2f(float x) {
    float r;
    asm("ex2.approx.f32 %0, %1;" : "=f"(r) : "f"(x));
    return r;
}
__device__ __forceinline__ float lg2f(float x) {
    float r;
    asm("lg2.approx.f32 %0, %1;" : "=f"(r) : "f"(x));
    return r;
}

// softplus contribution in SCALED space: given ss = s * (-log2e),
// softplus(s)/ln2 = lg2(1 + 2^{-|ss|}) - min(ss, 0).  (sum, then × LN2 once)
__device__ __forceinline__ float softplus_scaled(float ss) {
    float e = ex2f(fminf(ss, -ss));        // 2^{-|ss|}
    float lg = lg2f(1.0f + e);
    return lg - fminf(ss, 0.0f);
}

// Bernoulli accept test: u < sigmoid(s), u = bits·2^-32, sigmoid = 1/(1+ex).
// u(1+ex) < 1  <=>  bf + bf·ex < 2^32  with bf = (float)bits (I2F on cvt pipe)
__device__ __forceinline__ bool bern(uint32_t bits, float ex) {
    float bf = __uint2float_rn(bits);
    return fmaf(bf, ex, bf) < TWO32F;
}

// packed fp32x2 helpers (per-lane .rn rounding)
__device__ __forceinline__ void ffma2(u64& a, u64 b, u64 c) {
    asm("fma.rn.f32x2 %0, %1, %2, %0;" : "+l"(a) : "l"(b), "l"(c));
}
__device__ __forceinline__ u64 fadd2(u64 a, u64 b) {
    u64 r;
    asm("add.rn.f32x2 %0, %1, %2;" : "=l"(r) : "l"(a), "l"(b));
    return r;
}
__device__ __forceinline__ u64 fmul2(u64 a, u64 b) {
    u64 r;
    asm("mul.rn.f32x2 %0, %1, %2;" : "=l"(r) : "l"(a), "l"(b));
    return r;
}
__device__ __forceinline__ u64 dup2(float h) {
    u64 r;
    asm("mov.b64 %0, {%1, %1};" : "=l"(r) : "r"(__float_as_uint(h)));
    return r;
}
__device__ __forceinline__ u64 pack2(float a, float b) {
    u64 r;
    asm("mov.b64 %0, {%1, %2};" : "=l"(r) : "r"(__float_as_uint(a)), "r"(__float_as_uint(b)));
    return r;
}
__device__ __forceinline__ float lo32f(u64 v) { return __uint_as_float((uint32_t)v); }
__device__ __forceinline__ float hi32f(u64 v) { return __uint_as_float((uint32_t)(v >> 32)); }

union U128 { uint4 q; u64 u[2]; };

// ---------------------------------------------------------------------------
// free energy from SCALED (×-log2e) weights/mods; unscale with ×(-ln2)/×ln2
// ---------------------------------------------------------------------------
__device__ __forceinline__ float free_energy(const u64 vpack[8],
                                             const u64* sbmod_col,    // stride TPB
                                             const u64* scmodp_col,   // stride TPB
                                             const u64* sWtI) {
    u64 e2 = 0ull;
#pragma unroll
    for (int p = 0; p < 8; ++p) ffma2(e2, vpack[p], sbmod_col[p * TPB]);
    float e = (lo32f(e2) + hi32f(e2)) * NLN2;

    float dsum = 0.0f;   // sum of softplus/ln2 terms
#pragma unroll 2
    for (int jp = 0; jp < 16; ++jp) {
        u64 cpair = scmodp_col[jp * TPB];
#pragma unroll
        for (int sub = 0; sub < 2; ++sub) {
            int j = 2 * jp + sub;
            float cj = sub ? hi32f(cpair) : lo32f(cpair);
            u64 sp = pack2(cj, 0.0f);
            const u64* wI = &sWtI[j * 8];
#pragma unroll
            for (int p = 0; p < 8; ++p) ffma2(sp, vpack[p], wI[p]);
            dsum += softplus_scaled(lo32f(sp) + hi32f(sp));
        }
    }
    return -e - LN2 * dsum;
}

// ---------------------------------------------------------------------------
// single fused kernel — 1-draw software-pipelined threefry: draw j+1's RNG
// chain is issued during draw j's body, removing it from the critical path.
// ---------------------------------------------------------------------------
__global__ void __launch_bounds__(TPB, 6)
rbm_fused(const float* __restrict__ v_data,
          const float* __restrict__ cond,
          const float* __restrict__ W,
          const float* __restrict__ bias_b,
          const float* __restrict__ bias_c,
          const float* __restrict__ W1,
          const float* __restrict__ b1,
          const float* __restrict__ W2,
          const float* __restrict__ b2,
          const int* __restrict__ kp,
          float* __restrict__ out,
          int batch) {
    // union region: phase A = folded MLP matrix sM (12KB);
    // phase B = per-thread mod columns (8+16 u64 per thread = 24KB)
    __shared__ __align__(16) u64 sDyn[24 * TPB];   // 24KB
    __shared__ __align__(16) u64 sWtI[NH * 8];     // scaled weight pairs, 2KB
    __shared__ float sBase[48];
    __shared__ float sW1[64], sb1[64];
    __shared__ uint2 sck[MAXK];
    __shared__ uint2 sk1[MAXK], sk2[MAXK];
    __shared__ int   skk;
    __shared__ float swarp[TPB / 32];
    __shared__ int   sIsLast;
    __shared__ double sd[TPB];

    const int t = threadIdx.x;
    float* sMf = reinterpret_cast<float*>(sDyn);   // phase A view

    // ---- per-block init (redundant across blocks; cheap) ----
    for (int idx = t; idx < NH * 8; idx += TPB) {
        int j = idx / 8, p = idx % 8;
        sWtI[idx] = pack2(W[(2 * p) * NH + j] * NEG_LOG2E,
                          W[(2 * p + 1) * NH + j] * NEG_LOG2E);
    }
    for (int idx = t; idx < 64 * 48; idx += TPB) {
        int j = idx / 48, q = idx % 48;
        float m;
        if (q < NV) {
            m = bias_b[q] * W2[j * 96 + q] + W2[j * 96 + 16 + q];
        } else {
            int l = q - NV;
            m = bias_c[l] * W2[j * 96 + 32 + l] + W2[j * 96 + 64 + l];
        }
        sMf[idx] = m;
    }
    if (t < 48) {
        float bs;
        if (t < NV) bs = bias_b[t] * (1.0f + b2[t]) + b2[16 + t];
        else {
            int l = t - NV;
            bs = bias_c[l] * (1.0f + b2[32 + l]) + b2[64 + l];
        }
        sBase[t] = bs;
    }
    if (t < 64) { sW1[t] = W1[t]; sb1[t] = b1[t]; }
    if (t == 0) {
        int kkv = *kp;
        if (kkv < 0) kkv = 0;
        if (kkv > MAXK) kkv = MAXK;
        skk = kkv;
        uint2 key = make_uint2(0u, 42u);
        for (int s = 0; s < kkv; ++s) {
            sck[s] = key;
            key = tf2x32(key, 0u, 0u);
        }
    }
    __syncthreads();
    const int kk = skk;
    if (t < kk)                      sk1[t]      = tf2x32(sck[t],      0u, 1u);
    else if (t >= 64 && t < 64 + kk) sk2[t - 64] = tf2x32(sck[t - 64], 0u, 2u);
    __syncthreads();

    // ---- per-sample work ----
    const int sample = blockIdx.x * TPB + t;
    float loss = 0.0f;

    // phase A: conditioning MLP into registers (reads sM region)
    u64 modp[24];
    if (sample < batch) {
        float cb = cond[sample];
#pragma unroll
        for (int q = 0; q < 24; ++q) modp[q] = pack2(sBase[2 * q], sBase[2 * q + 1]);
        const u64* sM2 = sDyn;
#pragma unroll 4
        for (int j = 0; j < 64; ++j) {
            float tj = tanhf(fmaf(cb, sW1[j], sb1[j]));
            u64 tj2 = dup2(tj);
#pragma unroll
            for (int q = 0; q < 24; ++q) ffma2(modp[q], tj2, sM2[j * 24 + q]);
        }
    }
    __syncthreads();   // everyone done reading sM -> safe to overwrite

    // phase B: store SCALED mods into per-thread columns
    u64* sbmod_col  = &sDyn[t];             // 8 entries, stride TPB
    u64* scmodp_col = &sDyn[8 * TPB + t];   // 16 entries, stride TPB
    if (sample < batch) {
        const u64 sc2 = dup2(NEG_LOG2E);
#pragma unroll
        for (int p = 0; p < 8; ++p) sbmod_col[p * TPB] = fmul2(modp[p], sc2);
#pragma unroll
        for (int jp = 0; jp < 16; ++jp) scmodp_col[jp * TPB] = fmul2(modp[8 + jp], sc2);
    }

    if (sample < batch) {
        // load v_data as natural i-pairs
        u64 vpack[8];
        {
            const u64* vd = reinterpret_cast<const u64*>(v_data + (size_t)sample * NV);
#pragma unroll
            for (int p = 0; p < 8; ++p) vpack[p] = vd[p];
        }

        float fe_data = free_energy(vpack, sbmod_col, scmodp_col, sWtI);

        // ---- Gibbs chain ----
        const uint32_t base_h = (uint32_t)sample * NH;
        const uint32_t base_v = (uint32_t)sample * NV;

        for (int s = 0; s < kk; ++s) {
            const TFK K1 = mk_tfk(sk1[s]);
            const uint32_t hoff = base_h + K1.k1;
            u64 acc[8];
#pragma unroll
            for (int p = 0; p < 8; ++p) acc[p] = 0ull;

            // software pipeline: bits for draw j computed during draw j-1
            uint32_t bitsn = tf_bits_pc(K1, hoff);   // j = 0

#pragma unroll 2
            for (int jp = 0; jp < 16; ++jp) {
                u64 cpair = scmodp_col[jp * TPB];
#pragma unroll
                for (int sub = 0; sub < 2; ++sub) {
                    const int j = 2 * jp + sub;
                    uint32_t bits = bitsn;
                    // prefetch next draw's RNG (j=31 computes an unused j=32:
                    // 1 wasted threefry/step, cheaper than a branch in the loop)
                    bitsn = tf_bits_pc(K1, hoff + (uint32_t)(j + 1));
                    float cj = sub ? hi32f(cpair) : lo32f(cpair);
                    u64 sp = pack2(cj, 0.0f);
                    const U128* wq = reinterpret_cast<const U128*>(&sWtI[j * 8]);
                    U128 q0 = wq[0], q1 = wq[1], q2 = wq[2], q3 = wq[3];
                    ffma2(sp, vpack[0], q0.u[0]); ffma2(sp, vpack[1], q0.u[1]);
                    ffma2(sp, vpack[2], q1.u[0]); ffma2(sp, vpack[3], q1.u[1]);
                    ffma2(sp, vpack[4], q2.u[0]); ffma2(sp, vpack[5], q2.u[1]);
                    ffma2(sp, vpack[6], q3.u[0]); ffma2(sp, vpack[7], q3.u[1]);
                    // scaled dot -> e^{-s} directly
                    float ex = ex2f(lo32f(sp) + hi32f(sp));
                    u64 h2 = bern(bits, ex) ? ONES2 : 0ull;
                    ffma2(acc[0], h2, q0.u[0]); ffma2(acc[1], h2, q0.u[1]);
                    ffma2(acc[2], h2, q1.u[0]); ffma2(acc[3], h2, q1.u[1]);
                    ffma2(acc[4], h2, q2.u[0]); ffma2(acc[5], h2, q2.u[1]);
                    ffma2(acc[6], h2, q3.u[0]); ffma2(acc[7], h2, q3.u[1]);
                }
            }

            const TFK K2 = mk_tfk(sk2[s]);
            const uint32_t voff = base_v + K2.k1;
            // visible pipeline: p loop fully unrolled -> compile-time guard
            uint32_t nb0 = tf_bits_pc(K2, voff);
            uint32_t nb1 = tf_bits_pc(K2, voff + 1u);
#pragma unroll
            for (int p = 0; p < 8; ++p) {
                uint32_t b0 = nb0, b1 = nb1;
                if (p < 7) {
                    nb0 = tf_bits_pc(K2, voff + (uint32_t)(2 * p + 2));
                    nb1 = tf_bits_pc(K2, voff + (uint32_t)(2 * p + 3));
                }
                u64 sv2 = fadd2(acc[p], sbmod_col[p * TPB]);   // scaled space
                float e0 = ex2f(lo32f(sv2));
                float e1 = ex2f(hi32f(sv2));
                uint32_t v0 = bern(b0, e0) ? 0x3f800000u : 0u;
                uint32_t v1 = bern(b1, e1) ? 0x3f800000u : 0u;
                vpack[p] = pack2(__uint_as_float(v0), __uint_as_float(v1));
            }
        }

        float fe_model = free_energy(vpack, sbmod_col, scmodp_col, sWtI);
        loss = fe_data - fe_model;
    }

    // ---- deterministic block reduction ----
#pragma unroll
    for (int off = 16; off > 0; off >>= 1)
        loss += __shfl_down_sync(0xffffffffu, loss, off);
    if ((t & 31) == 0) swarp[t >> 5] = loss;
    __syncthreads();
    if (t == 0) {
        float tot = 0.0f;
#pragma unroll
        for (int wgi = 0; wgi < TPB / 32; ++wgi) tot += swarp[wgi];
        g_part[blockIdx.x] = tot;
        __threadfence();
        unsigned r = atomicAdd(&g_ticket, 1u);
        sIsLast = (r == gridDim.x - 1) ? 1 : 0;
    }
    __syncthreads();

    // ---- last block: final deterministic reduction ----
    if (sIsLast) {
        __threadfence();
        double accd = 0.0;
        for (int idx = t; idx < (int)gridDim.x; idx += TPB)
            accd += (double)g_part[idx];
        sd[t] = accd;
        __syncthreads();
#pragma unroll
        for (int off = TPB / 2; off > 0; off >>= 1) {
            if (t < off) sd[t] += sd[t + off];
            __syncthreads();
        }
        if (t == 0) {
            out[0] = (float)(sd[0] / (double)batch);
            g_ticket = 0u;   // reset for next graph replay
        }
    }
}

// ---------------------------------------------------------------------------
extern "C" void kernel_launch(void* const* d_in, const int* in_sizes, int n_in,
                              void* d_out, int out_size) {
    const float* v_data = (const float*)d_in[0];
    const float* cond   = (const float*)d_in[1];
    const float* W      = (const float*)d_in[2];
    const float* bias_b = (const float*)d_in[3];
    const float* bias_c = (const float*)d_in[4];
    const float* W1     = (const float*)d_in[5];
    const float* b1     = (const float*)d_in[6];
    const float* W2     = (const float*)d_in[7];
    const float* b2     = (const float*)d_in[8];
    const int*   kp     = (const int*)d_in[9];

    int batch = in_sizes[0] / NV;   // 524288
    int grid = (batch + TPB - 1) / TPB;
    if (grid > MAXBLK) grid = MAXBLK;

    rbm_fused<<<grid, TPB>>>(v_data, cond, W, bias_b, bias_c, W1, b1, W2, b2,
                             kp, (float*)d_out, batch);
}

// round 17
// speedup vs baseline: 1.0210x; 1.0210x over previous
#include <cuda_runtime.h>
#include <stdint.h>
#include <math.h>

// Inputs: 0 v_data f32[524288*16], 1 cond f32[524288], 2 W f32[16*32], 3 b f32[16],
// 4 c f32[32], 5 W1 f32[64], 6 b1 f32[64], 7 W2 f32[64*96], 8 b2 f32[96], 9 k int[1]
// output: f32[1]

#define NV 16
#define NH 32
#define TPB 128
#define MAXK 64
#define MAXBLK 8192

typedef unsigned long long u64;

#define NEG_LOG2E (-1.44269504088896340736f)
#define NLN2      (-0.69314718055994530942f)
#define LN2       (0.69314718055994530942f)
#define TWO32F    4294967296.0f
#define ONES2     0x3F8000003F800000ull

__device__ float g_part[MAXBLK];
__device__ unsigned int g_ticket;   // zero-init; reset by last block each launch

// ---------------------------------------------------------------------------
// threefry2x32 (JAX partitionable semantics, verified bit-exact)
// ---------------------------------------------------------------------------
__device__ __forceinline__ uint32_t rotl32(uint32_t x, int r) {
    return __funnelshift_l(x, x, r);
}

__device__ __forceinline__ uint2 tf2x32(uint2 key, uint32_t chi, uint32_t clo) {
    uint32_t k0 = key.x, k1 = key.y, k2 = k0 ^ k1 ^ 0x1BD11BDAu;
    uint32_t x0 = chi + k0, x1 = clo + k1;
#define TFR(r) { x0 += x1; x1 = rotl32(x1, r); x1 ^= x0; }
    TFR(13) TFR(15) TFR(26) TFR(6)   x0 += k1; x1 += k2 + 1u;
    TFR(17) TFR(29) TFR(16) TFR(24)  x0 += k2; x1 += k0 + 2u;
    TFR(13) TFR(15) TFR(26) TFR(6)   x0 += k0; x1 += k1 + 3u;
    TFR(17) TFR(29) TFR(16) TFR(24)  x0 += k1; x1 += k2 + 4u;
    TFR(13) TFR(15) TFR(26) TFR(6)   x0 += k2; x1 += k0 + 5u;
#undef TFR
    return make_uint2(x0, x1);
}

struct TFK { uint32_t k0, k1, k2, c1, c2, c3, c4, c5; };

__device__ __forceinline__ TFK mk_tfk(uint2 key) {
    TFK K;
    K.k0 = key.x; K.k1 = key.y; K.k2 = K.k0 ^ K.k1 ^ 0x1BD11BDAu;
    K.c1 = K.k2 + 1u; K.c2 = K.k0 + 2u; K.c3 = K.k1 + 3u;
    K.c4 = K.k2 + 4u; K.c5 = K.k0 + 5u;
    return K;
}

// x1init = idx + K.k1 precombined by caller (integer add exact)
__device__ __forceinline__ uint32_t tf_bits_pc(const TFK K, uint32_t x1init) {
    uint32_t x0 = K.k0, x1 = x1init;
#define TFR(r) { x0 += x1; x1 = rotl32(x1, r); x1 ^= x0; }
    TFR(13) TFR(15) TFR(26) TFR(6)   x0 += K.k1; x1 += K.c1;
    TFR(17) TFR(29) TFR(16) TFR(24)  x0 += K.k2; x1 += K.c2;
    TFR(13) TFR(15) TFR(26) TFR(6)   x0 += K.k0; x1 += K.c3;
    TFR(17) TFR(29) TFR(16) TFR(24)  x0 += K.k1; x1 += K.c4;
    TFR(13) TFR(15) TFR(26) TFR(6)   x0 += K.k2; x1 += K.c5;
#undef TFR
    return x0 ^ x1;
}

// raw ex2.approx: input pre-scaled by -log2e, result = e^{-s}
__device__ __forceinline__ float ex2f(float x) {
    float r;
    asm("ex2.approx.f32 %0, %1;" : "=f"(r) : "f"(x));
    return r;
}
__device__ __forceinline__ float lg2f(float x) {
    float r;
    asm("lg2.approx.f32 %0, %1;" : "=f"(r) : "f"(x));
    return r;
}

// softplus contribution in SCALED space: given ss = s * (-log2e),
// softplus(s)/ln2 = lg2(1 + 2^{-|ss|}) - min(ss, 0).  (sum, then × LN2 once)
__device__ __forceinline__ float softplus_scaled(float ss) {
    float e = ex2f(fminf(ss, -ss));        // 2^{-|ss|}
    float lg = lg2f(1.0f + e);
    return lg - fminf(ss, 0.0f);
}

// Bernoulli accept test: u < sigmoid(s), u = bits·2^-32, sigmoid = 1/(1+ex).
// u(1+ex) < 1  <=>  bf + bf·ex < 2^32  with bf = (float)bits (I2F on cvt pipe)
__device__ __forceinline__ bool bern(uint32_t bits, float ex) {
    float bf = __uint2float_rn(bits);
    return fmaf(bf, ex, bf) < TWO32F;
}

// packed fp32x2 helpers (per-lane .rn rounding)
__device__ __forceinline__ void ffma2(u64& a, u64 b, u64 c) {
    asm("fma.rn.f32x2 %0, %1, %2, %0;" : "+l"(a) : "l"(b), "l"(c));
}
__device__ __forceinline__ u64 fadd2(u64 a, u64 b) {
    u64 r;
    asm("add.rn.f32x2 %0, %1, %2;" : "=l"(r) : "l"(a), "l"(b));
    return r;
}
__device__ __forceinline__ u64 fmul2(u64 a, u64 b) {
    u64 r;
    asm("mul.rn.f32x2 %0, %1, %2;" : "=l"(r) : "l"(a), "l"(b));
    return r;
}
__device__ __forceinline__ u64 dup2(float h) {
    u64 r;
    asm("mov.b64 %0, {%1, %1};" : "=l"(r) : "r"(__float_as_uint(h)));
    return r;
}
__device__ __forceinline__ u64 pack2(float a, float b) {
    u64 r;
    asm("mov.b64 %0, {%1, %2};" : "=l"(r) : "r"(__float_as_uint(a)), "r"(__float_as_uint(b)));
    return r;
}
__device__ __forceinline__ float lo32f(u64 v) { return __uint_as_float((uint32_t)v); }
__device__ __forceinline__ float hi32f(u64 v) { return __uint_as_float((uint32_t)(v >> 32)); }

union U128 { uint4 q; u64 u[2]; };

// ---------------------------------------------------------------------------
// free energy from SCALED (×-log2e) weights/mods; unscale with ×(-ln2)/×ln2
// ---------------------------------------------------------------------------
__device__ __forceinline__ float free_energy(const u64 vpack[8],
                                             const u64* sbmod_col,    // stride TPB
                                             const u64* scmodp_col,   // stride TPB
                                             const u64* sWtI) {
    u64 e2 = 0ull;
#pragma unroll
    for (int p = 0; p < 8; ++p) ffma2(e2, vpack[p], sbmod_col[p * TPB]);
    float e = (lo32f(e2) + hi32f(e2)) * NLN2;

    float dsum = 0.0f;   // sum of softplus/ln2 terms
#pragma unroll 2
    for (int jp = 0; jp < 16; ++jp) {
        u64 cpair = scmodp_col[jp * TPB];
#pragma unroll
        for (int sub = 0; sub < 2; ++sub) {
            int j = 2 * jp + sub;
            float cj = sub ? hi32f(cpair) : lo32f(cpair);
            u64 sp = pack2(cj, 0.0f);
            const u64* wI = &sWtI[j * 8];
#pragma unroll
            for (int p = 0; p < 8; ++p) ffma2(sp, vpack[p], wI[p]);
            dsum += softplus_scaled(lo32f(sp) + hi32f(sp));
        }
    }
    return -e - LN2 * dsum;
}

// ---------------------------------------------------------------------------
// single fused kernel — pair-level threefry hoist: both draws' RNG chains of a
// j-pair start before the pair's weight loads / dot chains (no cross-iteration
// carry, no wasted draws — refinement of the R15 winner).
// ---------------------------------------------------------------------------
__global__ void __launch_bounds__(TPB, 6)
rbm_fused(const float* __restrict__ v_data,
          const float* __restrict__ cond,
          const float* __restrict__ W,
          const float* __restrict__ bias_b,
          const float* __restrict__ bias_c,
          const float* __restrict__ W1,
          const float* __restrict__ b1,
          const float* __restrict__ W2,
          const float* __restrict__ b2,
          const int* __restrict__ kp,
          float* __restrict__ out,
          int batch) {
    // union region: phase A = folded MLP matrix sM (12KB);
    // phase B = per-thread mod columns (8+16 u64 per thread = 24KB)
    __shared__ __align__(16) u64 sDyn[24 * TPB];   // 24KB
    __shared__ __align__(16) u64 sWtI[NH * 8];     // scaled weight pairs, 2KB
    __shared__ float sBase[48];
    __shared__ float sW1[64], sb1[64];
    __shared__ uint2 sck[MAXK];
    __shared__ uint2 sk1[MAXK], sk2[MAXK];
    __shared__ int   skk;
    __shared__ float swarp[TPB / 32];
    __shared__ int   sIsLast;
    __shared__ double sd[TPB];

    const int t = threadIdx.x;
    float* sMf = reinterpret_cast<float*>(sDyn);   // phase A view

    // ---- per-block init (redundant across blocks; cheap) ----
    for (int idx = t; idx < NH * 8; idx += TPB) {
        int j = idx / 8, p = idx % 8;
        sWtI[idx] = pack2(W[(2 * p) * NH + j] * NEG_LOG2E,
                          W[(2 * p + 1) * NH + j] * NEG_LOG2E);
    }
    for (int idx = t; idx < 64 * 48; idx += TPB) {
        int j = idx / 48, q = idx % 48;
        float m;
        if (q < NV) {
            m = bias_b[q] * W2[j * 96 + q] + W2[j * 96 + 16 + q];
        } else {
            int l = q - NV;
            m = bias_c[l] * W2[j * 96 + 32 + l] + W2[j * 96 + 64 + l];
        }
        sMf[idx] = m;
    }
    if (t < 48) {
        float bs;
        if (t < NV) bs = bias_b[t] * (1.0f + b2[t]) + b2[16 + t];
        else {
            int l = t - NV;
            bs = bias_c[l] * (1.0f + b2[32 + l]) + b2[64 + l];
        }
        sBase[t] = bs;
    }
    if (t < 64) { sW1[t] = W1[t]; sb1[t] = b1[t]; }
    if (t == 0) {
        int kkv = *kp;
        if (kkv < 0) kkv = 0;
        if (kkv > MAXK) kkv = MAXK;
        skk = kkv;
        uint2 key = make_uint2(0u, 42u);
        for (int s = 0; s < kkv; ++s) {
            sck[s] = key;
            key = tf2x32(key, 0u, 0u);
        }
    }
    __syncthreads();
    const int kk = skk;
    if (t < kk)                      sk1[t]      = tf2x32(sck[t],      0u, 1u);
    else if (t >= 64 && t < 64 + kk) sk2[t - 64] = tf2x32(sck[t - 64], 0u, 2u);
    __syncthreads();

    // ---- per-sample work ----
    const int sample = blockIdx.x * TPB + t;
    float loss = 0.0f;

    // phase A: conditioning MLP into registers (reads sM region)
    u64 modp[24];
    if (sample < batch) {
        float cb = cond[sample];
#pragma unroll
        for (int q = 0; q < 24; ++q) modp[q] = pack2(sBase[2 * q], sBase[2 * q + 1]);
        const u64* sM2 = sDyn;
#pragma unroll 4
        for (int j = 0; j < 64; ++j) {
            float tj = tanhf(fmaf(cb, sW1[j], sb1[j]));
            u64 tj2 = dup2(tj);
#pragma unroll
            for (int q = 0; q < 24; ++q) ffma2(modp[q], tj2, sM2[j * 24 + q]);
        }
    }
    __syncthreads();   // everyone done reading sM -> safe to overwrite

    // phase B: store SCALED mods into per-thread columns
    u64* sbmod_col  = &sDyn[t];             // 8 entries, stride TPB
    u64* scmodp_col = &sDyn[8 * TPB + t];   // 16 entries, stride TPB
    if (sample < batch) {
        const u64 sc2 = dup2(NEG_LOG2E);
#pragma unroll
        for (int p = 0; p < 8; ++p) sbmod_col[p * TPB] = fmul2(modp[p], sc2);
#pragma unroll
        for (int jp = 0; jp < 16; ++jp) scmodp_col[jp * TPB] = fmul2(modp[8 + jp], sc2);
    }

    if (sample < batch) {
        // load v_data as natural i-pairs
        u64 vpack[8];
        {
            const u64* vd = reinterpret_cast<const u64*>(v_data + (size_t)sample * NV);
#pragma unroll
            for (int p = 0; p < 8; ++p) vpack[p] = vd[p];
        }

        float fe_data = free_energy(vpack, sbmod_col, scmodp_col, sWtI);

        // ---- Gibbs chain ----
        const uint32_t base_h = (uint32_t)sample * NH;
        const uint32_t base_v = (uint32_t)sample * NV;

        for (int s = 0; s < kk; ++s) {
            const TFK K1 = mk_tfk(sk1[s]);
            const uint32_t hoff = base_h + K1.k1;
            u64 acc[8];
#pragma unroll
            for (int p = 0; p < 8; ++p) acc[p] = 0ull;

#pragma unroll 2
            for (int jp = 0; jp < 16; ++jp) {
                // PAIR-LEVEL HOIST: both draws' 160-cyc threefry chains start
                // before the pair's weight loads + dot chains (independent).
                const uint32_t jbase = hoff + (uint32_t)(2 * jp);
                uint32_t bits0 = tf_bits_pc(K1, jbase);
                uint32_t bits1 = tf_bits_pc(K1, jbase + 1u);
                u64 cpair = scmodp_col[jp * TPB];
#pragma unroll
                for (int sub = 0; sub < 2; ++sub) {
                    const int j = 2 * jp + sub;
                    uint32_t bits = sub ? bits1 : bits0;
                    float cj = sub ? hi32f(cpair) : lo32f(cpair);
                    u64 sp = pack2(cj, 0.0f);
                    const U128* wq = reinterpret_cast<const U128*>(&sWtI[j * 8]);
                    U128 q0 = wq[0], q1 = wq[1], q2 = wq[2], q3 = wq[3];
                    ffma2(sp, vpack[0], q0.u[0]); ffma2(sp, vpack[1], q0.u[1]);
                    ffma2(sp, vpack[2], q1.u[0]); ffma2(sp, vpack[3], q1.u[1]);
                    ffma2(sp, vpack[4], q2.u[0]); ffma2(sp, vpack[5], q2.u[1]);
                    ffma2(sp, vpack[6], q3.u[0]); ffma2(sp, vpack[7], q3.u[1]);
                    // scaled dot -> e^{-s} directly
                    float ex = ex2f(lo32f(sp) + hi32f(sp));
                    u64 h2 = bern(bits, ex) ? ONES2 : 0ull;
                    ffma2(acc[0], h2, q0.u[0]); ffma2(acc[1], h2, q0.u[1]);
                    ffma2(acc[2], h2, q1.u[0]); ffma2(acc[3], h2, q1.u[1]);
                    ffma2(acc[4], h2, q2.u[0]); ffma2(acc[5], h2, q2.u[1]);
                    ffma2(acc[6], h2, q3.u[0]); ffma2(acc[7], h2, q3.u[1]);
                }
            }

            const TFK K2 = mk_tfk(sk2[s]);
            const uint32_t voff = base_v + K2.k1;
#pragma unroll
            for (int p = 0; p < 8; ++p) {
                // per-iteration hoist (R15 winner form)
                uint32_t bits0 = tf_bits_pc(K2, voff + (uint32_t)(2 * p));
                uint32_t bits1 = tf_bits_pc(K2, voff + (uint32_t)(2 * p + 1));
                u64 sv2 = fadd2(acc[p], sbmod_col[p * TPB]);   // scaled space
                float e0 = ex2f(lo32f(sv2));
                float e1 = ex2f(hi32f(sv2));
                uint32_t v0 = bern(bits0, e0) ? 0x3f800000u : 0u;
                uint32_t v1 = bern(bits1, e1) ? 0x3f800000u : 0u;
                vpack[p] = pack2(__uint_as_float(v0), __uint_as_float(v1));
            }
        }

        float fe_model = free_energy(vpack, sbmod_col, scmodp_col, sWtI);
        loss = fe_data - fe_model;
    }

    // ---- deterministic block reduction ----
#pragma unroll
    for (int off = 16; off > 0; off >>= 1)
        loss += __shfl_down_sync(0xffffffffu, loss, off);
    if ((t & 31) == 0) swarp[t >> 5] = loss;
    __syncthreads();
    if (t == 0) {
        float tot = 0.0f;
#pragma unroll
        for (int wgi = 0; wgi < TPB / 32; ++wgi) tot += swarp[wgi];
        g_part[blockIdx.x] = tot;
        __threadfence();
        unsigned r = atomicAdd(&g_ticket, 1u);
        sIsLast = (r == gridDim.x - 1) ? 1 : 0;
    }
    __syncthreads();

    // ---- last block: final deterministic reduction ----
    if (sIsLast) {
        __threadfence();
        double accd = 0.0;
        for (int idx = t; idx < (int)gridDim.x; idx += TPB)
            accd += (double)g_part[idx];
        sd[t] = accd;
        __syncthreads();
#pragma unroll
        for (int off = TPB / 2; off > 0; off >>= 1) {
            if (t < off) sd[t] += sd[t + off];
            __syncthreads();
        }
        if (t == 0) {
            out[0] = (float)(sd[0] / (double)batch);
            g_ticket = 0u;   // reset for next graph replay
        }
    }
}

// ---------------------------------------------------------------------------
extern "C" void kernel_launch(void* const* d_in, const int* in_sizes, int n_in,
                              void* d_out, int out_size) {
    const float* v_data = (const float*)d_in[0];
    const float* cond   = (const float*)d_in[1];
    const float* W      = (const float*)d_in[2];
    const float* bias_b = (const float*)d_in[3];
    const float* bias_c = (const float*)d_in[4];
    const float* W1     = (const float*)d_in[5];
    const float* b1     = (const float*)d_in[6];
    const float* W2     = (const float*)d_in[7];
    const float* b2     = (const float*)d_in[8];
    const int*   kp     = (const int*)d_in[9];

    int batch = in_sizes[0] / NV;   // 524288
    int grid = (batch + TPB - 1) / TPB;
    if (grid > MAXBLK) grid = MAXBLK;

    rbm_fused<<<grid, TPB>>>(v_data, cond, W, bias_b, bias_c, W1, b1, W2, b2,
                             kp, (float*)d_out, batch);
}